// round 15
// baseline (speedup 1.0000x reference)
#include <cuda_runtime.h>
#include <cuda_bf16.h>

constexpr int N_NODES = 100000;
constexpr int N_EDGES = 3200000;
constexpr int F   = 32;
constexpr int L   = 50;
constexpr int EL  = 10;
constexpr int K   = 16;
constexpr int CAP = 96;          // ELL capacity (max degree ~60); multiple of 32-batching safe
constexpr int NW  = L * L * EL;  // 25000 weight entries

// Persistent scratch (static device arrays; zero-initialized at load).
// ELL slots beyond cnt[n] are NEVER written -> stay 0 -> weight-index field 0
// -> Wp[0] == 0.0f contributes nothing; src field 0 gathers row 0 harmlessly.
__device__ int            g_cnt[N_NODES];
__device__ unsigned char  g_lbl8[N_NODES];
__device__ unsigned       g_edata[(size_t)N_NODES * CAP];  // src(17b) | (widx+1)<<17
__device__ float          g_Wp0[NW + 1];                   // padded weights, [0]=0
__device__ float          g_Wp1[NW + 1];
__device__ float          g_Wp2[NW + 1];
__device__ float          g_hA[(size_t)N_NODES * F];       // fp32 h buffers
__device__ float          g_hB[(size_t)N_NODES * F];
__device__ float          g_sums[L * F];                   // zeroed by final_head

// ---------------------------------------------------------------------------
__global__ __launch_bounds__(256)
void prep_all(const int*   __restrict__ lbl,
              const float* __restrict__ W1,
              const float* __restrict__ W2,
              const float* __restrict__ W3)
{
    int i = blockIdx.x * blockDim.x + threadIdx.x;
    if (i < N_NODES) {
        g_lbl8[i] = (unsigned char)lbl[i];
        g_cnt[i]  = 0;
    }
    if (i <= NW) {
        g_Wp0[i] = (i == 0) ? 0.0f : W1[i - 1];
        g_Wp1[i] = (i == 0) ? 0.0f : W2[i - 1];
        g_Wp2[i] = (i == 0) ? 0.0f : W3[i - 1];
    }
}

// ---------------------------------------------------------------------------
__global__ __launch_bounds__(256)
void build_ell4(const int4* __restrict__ esrc4,
                const int4* __restrict__ edst4,
                const int4* __restrict__ elab4)
{
    int t = blockIdx.x * blockDim.x + threadIdx.x;
    if (t >= N_EDGES / 4) return;
    int4 s = __ldg(&esrc4[t]);
    int4 d = __ldg(&edst4[t]);
    int4 l = __ldg(&elab4[t]);

    unsigned w0 = ((unsigned)g_lbl8[s.x] * L + g_lbl8[d.x]) * EL + (unsigned)l.x + 1u;
    unsigned w1 = ((unsigned)g_lbl8[s.y] * L + g_lbl8[d.y]) * EL + (unsigned)l.y + 1u;
    unsigned w2 = ((unsigned)g_lbl8[s.z] * L + g_lbl8[d.z]) * EL + (unsigned)l.z + 1u;
    unsigned w3 = ((unsigned)g_lbl8[s.w] * L + g_lbl8[d.w]) * EL + (unsigned)l.w + 1u;

    int p0 = atomicAdd(&g_cnt[d.x], 1);
    int p1 = atomicAdd(&g_cnt[d.y], 1);
    int p2 = atomicAdd(&g_cnt[d.z], 1);
    int p3 = atomicAdd(&g_cnt[d.w], 1);

    g_edata[(size_t)d.x * CAP + p0] = (unsigned)s.x | (w0 << 17);
    g_edata[(size_t)d.y * CAP + p1] = (unsigned)s.y | (w1 << 17);
    g_edata[(size_t)d.z * CAP + p2] = (unsigned)s.z | (w2 << 17);
    g_edata[(size_t)d.w * CAP + p3] = (unsigned)s.w | (w3 << 17);
}

// ---------------------------------------------------------------------------
// Node accumulation, shuffle-fed: per 32-edge batch, lane loads record
// edata[batch+lane] (coalesced LDG.32) and its weight gather ONCE, off the
// critical path. Inner loop: one SHFL.IDX feeds all 4 groups their record,
// one SHFL their weight, then the row gather. Chain = 26 + 234 instead of
// record(234) -> weight(234) -> row(234).
// lane = 8*g + c; group g handles edge j+g; c = 4-float feature chunk.
// Padded slots (widx field 0) multiply by Wp[0]=0.
// ---------------------------------------------------------------------------
__device__ __forceinline__
float4 node_acc(const float* __restrict__ x_in,
                const float* __restrict__ Wp,
                const unsigned* __restrict__ edata,
                int cnt, int lane, int g, int c)
{
    const char* xb = (const char*)x_in + c * 16;     // per-lane 4-float chunk base
    float4 acc = make_float4(0.f, 0.f, 0.f, 0.f);
    int cnt_r = (cnt + 7) & ~7;

    for (int batch = 0; batch < cnt_r; batch += 32) {
        unsigned rec = __ldg(&edata[batch + lane]);  // batch+lane <= 95 < CAP
        float    wv  = __ldg(&Wp[rec >> 17]);
        int m = min(32, cnt_r - batch);
        #pragma unroll 2
        for (int j = 0; j < m; j += 8) {
            unsigned r0 = __shfl_sync(0xffffffffu, rec, j + g);
            float    w0 = __shfl_sync(0xffffffffu, wv,  j + g);
            unsigned r1 = __shfl_sync(0xffffffffu, rec, j + 4 + g);
            float    w1 = __shfl_sync(0xffffffffu, wv,  j + 4 + g);
            float4 a0 = __ldg(reinterpret_cast<const float4*>(
                                  xb + (size_t)(r0 & 0x1FFFFu) * 128u));
            float4 a1 = __ldg(reinterpret_cast<const float4*>(
                                  xb + (size_t)(r1 & 0x1FFFFu) * 128u));
            acc.x = fmaf(w0, a0.x, acc.x);
            acc.y = fmaf(w0, a0.y, acc.y);
            acc.z = fmaf(w0, a0.z, acc.z);
            acc.w = fmaf(w0, a0.w, acc.w);
            acc.x = fmaf(w1, a1.x, acc.x);
            acc.y = fmaf(w1, a1.y, acc.y);
            acc.z = fmaf(w1, a1.z, acc.z);
            acc.w = fmaf(w1, a1.w, acc.w);
        }
    }
    return acc;
}

__device__ __forceinline__
float4 reduce_groups(float4 a)
{
    #pragma unroll
    for (int m = 8; m <= 16; m <<= 1) {
        a.x += __shfl_xor_sync(0xffffffffu, a.x, m);
        a.y += __shfl_xor_sync(0xffffffffu, a.y, m);
        a.z += __shfl_xor_sync(0xffffffffu, a.z, m);
        a.w += __shfl_xor_sync(0xffffffffu, a.w, m);
    }
    return a;
}

// ---------------------------------------------------------------------------
__global__ __launch_bounds__(256)
void conv_ell(const float* __restrict__ x_in,
              float*       __restrict__ h_out,
              const float* __restrict__ Wp,
              const float* __restrict__ b)
{
    int n    = (blockIdx.x * blockDim.x + threadIdx.x) >> 5;
    int lane = threadIdx.x & 31;
    if (n >= N_NODES) return;
    int g = lane >> 3, c = lane & 7;

    int cnt = __ldg(&g_cnt[n]);
    float4 acc = node_acc(x_in, Wp, &g_edata[(size_t)n * CAP], cnt, lane, g, c);
    acc = reduce_groups(acc);

    if (g == 0) {
        float bias = b[g_lbl8[n]];
        float4 st;
        st.x = tanhf(acc.x + bias);
        st.y = tanhf(acc.y + bias);
        st.z = tanhf(acc.z + bias);
        st.w = tanhf(acc.w + bias);
        reinterpret_cast<float4*>(h_out)[(size_t)n * 8 + c] = st;
    }
}

// ---------------------------------------------------------------------------
__global__ __launch_bounds__(256)
void conv_ell_pool(const float* __restrict__ x_in,
                   const float* __restrict__ Wp,
                   const float* __restrict__ b)
{
    __shared__ float pool[L * F];
    for (int i = threadIdx.x; i < L * F; i += blockDim.x) pool[i] = 0.0f;
    __syncthreads();

    int lane = threadIdx.x & 31;
    int g = lane >> 3, c = lane & 7;
    int wpb = blockDim.x >> 5;
    int n0  = blockIdx.x * wpb + (threadIdx.x >> 5);
    int ns  = gridDim.x * wpb;

    for (int n = n0; n < N_NODES; n += ns) {
        int cnt = __ldg(&g_cnt[n]);
        float4 acc = node_acc(x_in, Wp, &g_edata[(size_t)n * CAP], cnt, lane, g, c);
        acc = reduce_groups(acc);
        if (g == 0) {
            int   l    = g_lbl8[n];
            float bias = b[l];
            atomicAdd(&pool[l * F + 4 * c + 0], tanhf(acc.x + bias));
            atomicAdd(&pool[l * F + 4 * c + 1], tanhf(acc.y + bias));
            atomicAdd(&pool[l * F + 4 * c + 2], tanhf(acc.z + bias));
            atomicAdd(&pool[l * F + 4 * c + 3], tanhf(acc.w + bias));
        }
    }
    __syncthreads();

    for (int i = threadIdx.x; i < L * F; i += blockDim.x)
        atomicAdd(&g_sums[i], pool[i]);
}

// ---------------------------------------------------------------------------
__global__ __launch_bounds__(512)
void final_head(const float* __restrict__ Wr,
                const float* __restrict__ br,
                float* __restrict__ out)
{
    __shared__ float red[512];
    int t = threadIdx.x;
    int k = t & 15;
    int chunk = t >> 4;

    float acc = 0.0f;
    for (int i = chunk; i < L * F; i += 32)
        acc += g_sums[i] * Wr[i * K + k];
    red[t] = acc;
    __syncthreads();

    #pragma unroll
    for (int s = 256; s >= 16; s >>= 1) {
        if (t < s) red[t] += red[t + s];
        __syncthreads();
    }
    if (t < K) out[t] = tanhf(red[t] + br[t]);
    __syncthreads();

    for (int i = t; i < L * F; i += 512) g_sums[i] = 0.0f;   // reset invariant
}

// ---------------------------------------------------------------------------
// inputs: 0:x 1:W1 2:b1 3:W2 4:b2 5:W3 6:b3 7:Wr 8:br 9:node_labels
//         10:edge_src 11:edge_dst 12:edge_labels
// ---------------------------------------------------------------------------
extern "C" void kernel_launch(void* const* d_in, const int* in_sizes, int n_in,
                              void* d_out, int out_size)
{
    const float* x   = (const float*)d_in[0];
    const float* W1  = (const float*)d_in[1];
    const float* b1  = (const float*)d_in[2];
    const float* W2  = (const float*)d_in[3];
    const float* b2  = (const float*)d_in[4];
    const float* W3  = (const float*)d_in[5];
    const float* b3  = (const float*)d_in[6];
    const float* Wr  = (const float*)d_in[7];
    const float* br  = (const float*)d_in[8];
    const int* lbl   = (const int*)d_in[9];
    const int* esrc  = (const int*)d_in[10];
    const int* edst  = (const int*)d_in[11];
    const int* elab  = (const int*)d_in[12];
    float* out = (float*)d_out;

    float *hA, *hB, *wp0, *wp1, *wp2;
    cudaGetSymbolAddress((void**)&hA,  g_hA);
    cudaGetSymbolAddress((void**)&hB,  g_hB);
    cudaGetSymbolAddress((void**)&wp0, g_Wp0);
    cudaGetSymbolAddress((void**)&wp1, g_Wp1);
    cudaGetSymbolAddress((void**)&wp2, g_Wp2);

    const int ng = (N_NODES + 255) / 256;            // 391
    const int bg = (N_EDGES / 4 + 255) / 256;        // 3125
    const int cg = (N_NODES * 32 + 255) / 256;       // warp per node

    prep_all<<<ng, 256>>>(lbl, W1, W2, W3);
    build_ell4<<<bg, 256>>>((const int4*)esrc, (const int4*)edst, (const int4*)elab);

    conv_ell<<<cg, 256>>>(x,  hA, wp0, b1);
    conv_ell<<<cg, 256>>>(hA, hB, wp1, b2);
    conv_ell_pool<<<1184, 256>>>(hB, wp2, b3);

    final_head<<<1, 512>>>(Wr, br, out);
}

// round 16
// speedup vs baseline: 1.1240x; 1.1240x over previous
#include <cuda_runtime.h>
#include <cuda_bf16.h>

constexpr int N_NODES = 100000;
constexpr int N_EDGES = 3200000;
constexpr int F   = 32;
constexpr int L   = 50;
constexpr int EL  = 10;
constexpr int K   = 16;
constexpr int CAP = 96;          // ELL capacity (max degree ~60); multiple of 8
constexpr int NW  = L * L * EL;  // 25000 weight entries

// Persistent scratch (static device arrays; zero-initialized at load).
// ELL slots beyond cnt[n] are NEVER written -> stay 0 -> weight-index field 0
// -> Wp[0] == 0.0f contributes nothing; src field 0 gathers row 0 harmlessly.
__device__ int            g_cnt[N_NODES];
__device__ unsigned char  g_lbl8[N_NODES];
__device__ unsigned       g_edata[(size_t)N_NODES * CAP];  // src(17b) | (widx+1)<<17
__device__ float          g_Wp0[NW + 1];                   // padded weights, [0]=0
__device__ float          g_Wp1[NW + 1];
__device__ float          g_Wp2[NW + 1];
__device__ float          g_hA[(size_t)N_NODES * F];       // fp32 h buffers
__device__ float          g_hB[(size_t)N_NODES * F];
__device__ float          g_sums[L * F];                   // zeroed by final_head

// ---------------------------------------------------------------------------
__global__ __launch_bounds__(256)
void prep_all(const int*   __restrict__ lbl,
              const float* __restrict__ W1,
              const float* __restrict__ W2,
              const float* __restrict__ W3)
{
    int i = blockIdx.x * blockDim.x + threadIdx.x;
    if (i < N_NODES) {
        g_lbl8[i] = (unsigned char)lbl[i];
        g_cnt[i]  = 0;
    }
    if (i <= NW) {
        g_Wp0[i] = (i == 0) ? 0.0f : W1[i - 1];
        g_Wp1[i] = (i == 0) ? 0.0f : W2[i - 1];
        g_Wp2[i] = (i == 0) ? 0.0f : W3[i - 1];
    }
}

// ---------------------------------------------------------------------------
__global__ __launch_bounds__(256)
void build_ell4(const int4* __restrict__ esrc4,
                const int4* __restrict__ edst4,
                const int4* __restrict__ elab4)
{
    int t = blockIdx.x * blockDim.x + threadIdx.x;
    if (t >= N_EDGES / 4) return;
    int4 s = __ldg(&esrc4[t]);
    int4 d = __ldg(&edst4[t]);
    int4 l = __ldg(&elab4[t]);

    unsigned w0 = ((unsigned)g_lbl8[s.x] * L + g_lbl8[d.x]) * EL + (unsigned)l.x + 1u;
    unsigned w1 = ((unsigned)g_lbl8[s.y] * L + g_lbl8[d.y]) * EL + (unsigned)l.y + 1u;
    unsigned w2 = ((unsigned)g_lbl8[s.z] * L + g_lbl8[d.z]) * EL + (unsigned)l.z + 1u;
    unsigned w3 = ((unsigned)g_lbl8[s.w] * L + g_lbl8[d.w]) * EL + (unsigned)l.w + 1u;

    int p0 = atomicAdd(&g_cnt[d.x], 1);
    int p1 = atomicAdd(&g_cnt[d.y], 1);
    int p2 = atomicAdd(&g_cnt[d.z], 1);
    int p3 = atomicAdd(&g_cnt[d.w], 1);

    g_edata[(size_t)d.x * CAP + p0] = (unsigned)s.x | (w0 << 17);
    g_edata[(size_t)d.y * CAP + p1] = (unsigned)s.y | (w1 << 17);
    g_edata[(size_t)d.z * CAP + p2] = (unsigned)s.z | (w2 << 17);
    g_edata[(size_t)d.w * CAP + p3] = (unsigned)s.w | (w3 << 17);
}

// ---------------------------------------------------------------------------
// Node accumulation: 8 edges per iteration, lane = 8*g + c.
// Group g handles edges (j+2g, j+2g+1): one LDG.64 fetches both records.
// fp32 feature rows: one LDG.128 per edge per lane, zero unpack ALU.
// No tail predication: padded slots have weight-index 0 -> Wp[0] = 0.
// ---------------------------------------------------------------------------
__device__ __forceinline__
float4 node_acc(const float* __restrict__ x_in,
                const float* __restrict__ Wp,
                const unsigned* __restrict__ edata,
                int cnt, int g, int c)
{
    const char* xb = (const char*)x_in + c * 16;     // per-lane 4-float chunk base
    const uint2* ed2 = reinterpret_cast<const uint2*>(edata);
    float4 acc = make_float4(0.f, 0.f, 0.f, 0.f);
    int cnt_r = (cnt + 7) & ~7;
    #pragma unroll 2
    for (int j = 0; j < cnt_r; j += 8) {
        uint2 rr = __ldg(&ed2[(j >> 1) + g]);        // records j+2g, j+2g+1
        float w0 = __ldg(&Wp[rr.x >> 17]);
        float w1 = __ldg(&Wp[rr.y >> 17]);
        float4 a0 = __ldg(reinterpret_cast<const float4*>(xb + (size_t)(rr.x & 0x1FFFFu) * 128u));
        float4 a1 = __ldg(reinterpret_cast<const float4*>(xb + (size_t)(rr.y & 0x1FFFFu) * 128u));
        acc.x = fmaf(w0, a0.x, acc.x);
        acc.y = fmaf(w0, a0.y, acc.y);
        acc.z = fmaf(w0, a0.z, acc.z);
        acc.w = fmaf(w0, a0.w, acc.w);
        acc.x = fmaf(w1, a1.x, acc.x);
        acc.y = fmaf(w1, a1.y, acc.y);
        acc.z = fmaf(w1, a1.z, acc.z);
        acc.w = fmaf(w1, a1.w, acc.w);
    }
    return acc;
}

__device__ __forceinline__
float4 reduce_groups(float4 a)
{
    #pragma unroll
    for (int m = 8; m <= 16; m <<= 1) {
        a.x += __shfl_xor_sync(0xffffffffu, a.x, m);
        a.y += __shfl_xor_sync(0xffffffffu, a.y, m);
        a.z += __shfl_xor_sync(0xffffffffu, a.z, m);
        a.w += __shfl_xor_sync(0xffffffffu, a.w, m);
    }
    return a;
}

// ---------------------------------------------------------------------------
// conv layers 1,2
// ---------------------------------------------------------------------------
__global__ __launch_bounds__(256)
void conv_ell(const float* __restrict__ x_in,
              float*       __restrict__ h_out,
              const float* __restrict__ Wp,
              const float* __restrict__ b)
{
    int n    = (blockIdx.x * blockDim.x + threadIdx.x) >> 5;
    int lane = threadIdx.x & 31;
    if (n >= N_NODES) return;
    int g = lane >> 3, c = lane & 7;

    int cnt = __ldg(&g_cnt[n]);
    float4 acc = node_acc(x_in, Wp, &g_edata[(size_t)n * CAP], cnt, g, c);
    acc = reduce_groups(acc);

    if (g == 0) {
        float bias = b[g_lbl8[n]];
        float4 st;
        st.x = tanhf(acc.x + bias);
        st.y = tanhf(acc.y + bias);
        st.z = tanhf(acc.z + bias);
        st.w = tanhf(acc.w + bias);
        reinterpret_cast<float4*>(h_out)[(size_t)n * 8 + c] = st;
    }
}

// ---------------------------------------------------------------------------
// conv layer 3 fused with label pooling: identical shape to conv_ell
// (one node per warp), epilogue = one red.global.add.v4.f32 per g==0 lane
// straight into g_sums. No smem pool, no node loop, no flush.
// ---------------------------------------------------------------------------
__global__ __launch_bounds__(256)
void conv_ell_red(const float* __restrict__ x_in,
                  const float* __restrict__ Wp,
                  const float* __restrict__ b)
{
    int n    = (blockIdx.x * blockDim.x + threadIdx.x) >> 5;
    int lane = threadIdx.x & 31;
    if (n >= N_NODES) return;
    int g = lane >> 3, c = lane & 7;

    int cnt = __ldg(&g_cnt[n]);
    float4 acc = node_acc(x_in, Wp, &g_edata[(size_t)n * CAP], cnt, g, c);
    acc = reduce_groups(acc);

    if (g == 0) {
        int   l    = g_lbl8[n];
        float bias = b[l];
        float v0 = tanhf(acc.x + bias);
        float v1 = tanhf(acc.y + bias);
        float v2 = tanhf(acc.z + bias);
        float v3 = tanhf(acc.w + bias);
        float* dst = &g_sums[l * F + 4 * c];
        asm volatile("red.global.add.v4.f32 [%0], {%1,%2,%3,%4};"
                     :: "l"(dst), "f"(v0), "f"(v1), "f"(v2), "f"(v3)
                     : "memory");
    }
}

// ---------------------------------------------------------------------------
__global__ __launch_bounds__(512)
void final_head(const float* __restrict__ Wr,
                const float* __restrict__ br,
                float* __restrict__ out)
{
    __shared__ float red[512];
    int t = threadIdx.x;
    int k = t & 15;
    int chunk = t >> 4;

    float acc = 0.0f;
    for (int i = chunk; i < L * F; i += 32)
        acc += g_sums[i] * Wr[i * K + k];
    red[t] = acc;
    __syncthreads();

    #pragma unroll
    for (int s = 256; s >= 16; s >>= 1) {
        if (t < s) red[t] += red[t + s];
        __syncthreads();
    }
    if (t < K) out[t] = tanhf(red[t] + br[t]);
    __syncthreads();

    for (int i = t; i < L * F; i += 512) g_sums[i] = 0.0f;   // reset invariant
}

// ---------------------------------------------------------------------------
// inputs: 0:x 1:W1 2:b1 3:W2 4:b2 5:W3 6:b3 7:Wr 8:br 9:node_labels
//         10:edge_src 11:edge_dst 12:edge_labels
// ---------------------------------------------------------------------------
extern "C" void kernel_launch(void* const* d_in, const int* in_sizes, int n_in,
                              void* d_out, int out_size)
{
    const float* x   = (const float*)d_in[0];
    const float* W1  = (const float*)d_in[1];
    const float* b1  = (const float*)d_in[2];
    const float* W2  = (const float*)d_in[3];
    const float* b2  = (const float*)d_in[4];
    const float* W3  = (const float*)d_in[5];
    const float* b3  = (const float*)d_in[6];
    const float* Wr  = (const float*)d_in[7];
    const float* br  = (const float*)d_in[8];
    const int* lbl   = (const int*)d_in[9];
    const int* esrc  = (const int*)d_in[10];
    const int* edst  = (const int*)d_in[11];
    const int* elab  = (const int*)d_in[12];
    float* out = (float*)d_out;

    float *hA, *hB, *wp0, *wp1, *wp2;
    cudaGetSymbolAddress((void**)&hA,  g_hA);
    cudaGetSymbolAddress((void**)&hB,  g_hB);
    cudaGetSymbolAddress((void**)&wp0, g_Wp0);
    cudaGetSymbolAddress((void**)&wp1, g_Wp1);
    cudaGetSymbolAddress((void**)&wp2, g_Wp2);

    const int ng = (N_NODES + 255) / 256;            // 391
    const int bg = (N_EDGES / 4 + 255) / 256;        // 3125
    const int cg = (N_NODES * 32 + 255) / 256;       // warp per node

    prep_all<<<ng, 256>>>(lbl, W1, W2, W3);
    build_ell4<<<bg, 256>>>((const int4*)esrc, (const int4*)edst, (const int4*)elab);

    conv_ell<<<cg, 256>>>(x,  hA, wp0, b1);
    conv_ell<<<cg, 256>>>(hA, hB, wp1, b2);
    conv_ell_red<<<cg, 256>>>(hB, wp2, b3);

    final_head<<<1, 512>>>(Wr, br, out);
}